// round 2
// baseline (speedup 1.0000x reference)
#include <cuda_runtime.h>
#include <math.h>

// Problem shape (fixed by the dataset): B=2, H=12, S=1024, D=64
#define BB 2
#define HH 12
#define SS 1024
#define DD 64
#define KP 102          // k_precise = int(1024 * 0.1)
#define NROWS (BB*HH*SS)   // 24576

__device__ unsigned long long g_qbits[NROWS];
__device__ unsigned long long g_kbits[NROWS];

// ---------------------------------------------------------------------------
// Kernel 1: pack sign bits. One warp per row; lane l holds d=l and d=l+32.
// bit = (x > 0)  (sign(+)=+1, sign(-)=-1; exact zeros have measure ~0).
// ---------------------------------------------------------------------------
__global__ void pack_signs_kernel(const float* __restrict__ q,
                                  const float* __restrict__ k) {
    int warp = (blockIdx.x * blockDim.x + threadIdx.x) >> 5;
    int lane = threadIdx.x & 31;
    if (warp >= 2 * NROWS) return;

    const float* src;
    unsigned long long* dst;
    int row;
    if (warp < NROWS) { src = q; dst = g_qbits; row = warp; }
    else              { src = k; dst = g_kbits; row = warp - NROWS; }

    const float* p = src + (size_t)row * DD;
    unsigned lo = __ballot_sync(0xffffffffu, p[lane]        > 0.0f);
    unsigned hi = __ballot_sync(0xffffffffu, p[lane + 32]   > 0.0f);
    if (lane == 0)
        dst[row] = (unsigned long long)lo | ((unsigned long long)hi << 32);
}

// ---------------------------------------------------------------------------
// Kernel 2: one CTA (128 threads = 4 warps) per query.
//   Phase A: popcounts vs all 1024 keys + 65-bin histogram
//   Phase B: counting-select top-102 (tie-break: lowest index, matching
//            jax.lax.top_k stable ordering)
//   Phase C: precise scores (q.k/8 + mask), softmax, weighted v sum
// ---------------------------------------------------------------------------
__global__ __launch_bounds__(128, 8)
void attn_kernel(const float* __restrict__ q,
                 const float* __restrict__ k,
                 const float* __restrict__ v,
                 const float* __restrict__ mask,
                 float* __restrict__ out) {
    __shared__ unsigned long long s_kb[SS];      // 8 KB
    __shared__ unsigned char     s_popc[SS];     // 1 KB
    __shared__ int               s_hist[65];
    __shared__ int               s_idx[KP];
    __shared__ float             s_score[KP];    // scores, then probs (unnorm)
    __shared__ float             s_q[DD];
    __shared__ float             s_red[4];
    __shared__ float             s_acc[128];
    __shared__ int               s_thresh[2];    // p*, r
    __shared__ int               s_count;

    const int qid  = blockIdx.x;        // 0..B*H*S-1
    const int bh   = qid >> 10;         // /S
    const int b    = bh / HH;
    const int tid  = threadIdx.x;
    const int lane = tid & 31;
    const int w    = tid >> 5;

    const unsigned long long  qbit = g_qbits[qid];
    const unsigned long long* kb   = g_kbits + (size_t)bh * SS;

    // ---- load packed key bits, init histogram ----
    for (int i = tid; i < SS; i += 128) s_kb[i] = kb[i];
    if (tid < 65) s_hist[tid] = 0;
    if (tid == 0) s_count = 0;
    __syncthreads();

    // ---- Phase A: popcounts + histogram ----
    for (int i = tid; i < SS; i += 128) {
        int p = __popcll(qbit ^ s_kb[i]);
        s_popc[i] = (unsigned char)p;
        atomicAdd(&s_hist[p], 1);
    }
    __syncthreads();

    // ---- threshold: smallest p* with cum >= KP ----
    if (tid == 0) {
        int c = 0, pstar = 64, cl = 0;
        for (int p = 0; p <= 64; ++p) {
            int nc = c + s_hist[p];
            if (nc >= KP) { pstar = p; cl = c; break; }
            c = nc;
        }
        s_thresh[0] = pstar;
        s_thresh[1] = KP - cl;   // r keys to take at the tie level
    }
    __syncthreads();
    const int pstar = s_thresh[0];
    const int r     = s_thresh[1];

    // ---- Phase B1: all keys strictly above threshold (set semantics) ----
    for (int i = tid; i < SS; i += 128) {
        if ((int)s_popc[i] < pstar) {
            int pos = atomicAdd(&s_count, 1);
            s_idx[pos] = i;
        }
    }
    __syncthreads();

    // ---- Phase B2: first r tied keys by ascending index (warp 0 scan) ----
    if (w == 0) {
        const int base = s_count;       // == KP - r
        int taken = 0;
        for (int c0 = 0; c0 < SS && taken < r; c0 += 32) {
            int i = c0 + lane;
            bool eq = ((int)s_popc[i] == pstar);
            unsigned ball = __ballot_sync(0xffffffffu, eq);
            int pre = __popc(ball & ((1u << lane) - 1u));
            if (eq && (taken + pre) < r)
                s_idx[base + taken + pre] = i;
            taken += __popc(ball);
        }
    }

    // ---- load q row ----
    const float* qrow = q + (size_t)qid * DD;
    if (tid < DD) s_q[tid] = qrow[tid];
    __syncthreads();

    // ---- Phase C1: precise scores ----
    const float* kbase = k + (size_t)bh * SS * DD;
    const float* mrow  = mask + (size_t)b * SS;
    for (int j = w; j < KP; j += 4) {
        const int idx = s_idx[j];
        const float* krow = kbase + (size_t)idx * DD;
        float part = s_q[lane] * krow[lane] + s_q[lane + 32] * krow[lane + 32];
        #pragma unroll
        for (int off = 16; off; off >>= 1)
            part += __shfl_xor_sync(0xffffffffu, part, off);
        if (lane == 0)
            s_score[j] = part * 0.125f + mrow[idx];
    }
    __syncthreads();

    // ---- softmax max ----
    float val = (tid < KP) ? s_score[tid] : -INFINITY;
    #pragma unroll
    for (int off = 16; off; off >>= 1)
        val = fmaxf(val, __shfl_xor_sync(0xffffffffu, val, off));
    if (lane == 0) s_red[w] = val;
    __syncthreads();
    const float m = fmaxf(fmaxf(s_red[0], s_red[1]), fmaxf(s_red[2], s_red[3]));
    __syncthreads();

    // ---- exp + sum ----
    float e = (tid < KP) ? __expf(s_score[tid] - m) : 0.0f;
    if (tid < KP) s_score[tid] = e;
    float sm = e;
    #pragma unroll
    for (int off = 16; off; off >>= 1)
        sm += __shfl_xor_sync(0xffffffffu, sm, off);
    if (lane == 0) s_red[w] = sm;
    __syncthreads();
    const float inv = 1.0f / (s_red[0] + s_red[1] + s_red[2] + s_red[3]);

    // ---- Phase C2: weighted v accumulation ----
    // threads [0,64) = dims for keys [0,51); threads [64,128) = dims for [51,102)
    const float* vbase = v + (size_t)bh * SS * DD;
    const int d  = tid & 63;
    const int g  = tid >> 6;
    const int j0 = g ? 51 : 0;
    const int j1 = g ? KP : 51;
    float acc = 0.0f;
    for (int j = j0; j < j1; ++j)
        acc += s_score[j] * vbase[(size_t)s_idx[j] * DD + d];
    s_acc[tid] = acc;
    __syncthreads();
    if (tid < DD)
        out[(size_t)qid * DD + tid] = (s_acc[tid] + s_acc[tid + 64]) * inv;
}

// ---------------------------------------------------------------------------
extern "C" void kernel_launch(void* const* d_in, const int* in_sizes, int n_in,
                              void* d_out, int out_size) {
    const float* q    = (const float*)d_in[0];
    const float* k    = (const float*)d_in[1];
    const float* v    = (const float*)d_in[2];
    const float* mask = (const float*)d_in[3];
    float* out        = (float*)d_out;

    // pack: 2*NROWS warps, 256 threads/block
    {
        int total_threads = 2 * NROWS * 32;
        int block = 256;
        int grid = (total_threads + block - 1) / block;
        pack_signs_kernel<<<grid, block>>>(q, k);
    }
    // attention: one block per query
    attn_kernel<<<NROWS, 128>>>(q, k, v, mask, out);
}

// round 3
// speedup vs baseline: 1.4206x; 1.4206x over previous
#include <cuda_runtime.h>
#include <math.h>

// Problem shape (fixed by the dataset): B=2, H=12, S=1024, D=64
#define BB 2
#define HH 12
#define SS 1024
#define DD 64
#define KP 102          // k_precise = int(1024 * 0.1)
#define NROWS (BB*HH*SS)   // 24576

__device__ unsigned long long g_qbits[NROWS];
__device__ unsigned long long g_kbits[NROWS];

// ---------------------------------------------------------------------------
// Kernel 1: pack sign bits. One warp per row; lane l holds d=l and d=l+32.
// ---------------------------------------------------------------------------
__global__ void pack_signs_kernel(const float* __restrict__ q,
                                  const float* __restrict__ k) {
    int warp = (blockIdx.x * blockDim.x + threadIdx.x) >> 5;
    int lane = threadIdx.x & 31;
    if (warp >= 2 * NROWS) return;

    const float* src;
    unsigned long long* dst;
    int row;
    if (warp < NROWS) { src = q; dst = g_qbits; row = warp; }
    else              { src = k; dst = g_kbits; row = warp - NROWS; }

    const float* p = src + (size_t)row * DD;
    unsigned lo = __ballot_sync(0xffffffffu, p[lane]        > 0.0f);
    unsigned hi = __ballot_sync(0xffffffffu, p[lane + 32]   > 0.0f);
    if (lane == 0)
        dst[row] = (unsigned long long)lo | ((unsigned long long)hi << 32);
}

// ---------------------------------------------------------------------------
// Kernel 2: one CTA (128 threads = 4 warps) per query.
// ---------------------------------------------------------------------------
__global__ __launch_bounds__(128, 8)
void attn_kernel(const float* __restrict__ q,
                 const float* __restrict__ k,
                 const float* __restrict__ v,
                 const float* __restrict__ mask,
                 float* __restrict__ out) {
    __shared__ unsigned char s_popc[SS];     // 1 KB
    __shared__ int           s_hist[65];
    __shared__ int           s_idx[KP];
    __shared__ float         s_score[KP];    // scores -> unnormalized probs
    __shared__ float4        s_q4[16];       // q row as float4
    __shared__ float         s_red[4];
    __shared__ float         s_accf[8][64];  // 2 KB: partial v sums
    __shared__ int           s_thresh[2];    // p*, r
    __shared__ int           s_count;

    const int qid  = blockIdx.x;        // 0..B*H*S-1
    const int bh   = qid >> 10;         // /S
    const int b    = bh / HH;
    const int tid  = threadIdx.x;
    const int lane = tid & 31;
    const int w    = tid >> 5;
    const unsigned full = 0xffffffffu;

    const unsigned long long  qbit = g_qbits[qid];
    const unsigned long long* kb   = g_kbits + (size_t)bh * SS;

    if (tid < 65) s_hist[tid] = 0;
    if (tid == 0) s_count = 0;
    // load q row (as float4) early
    if (tid < 16) s_q4[tid] = ((const float4*)(q + (size_t)qid * DD))[tid];
    __syncthreads();

    // ---- Phase A: popcounts straight from global + aggregated histogram ----
    #pragma unroll
    for (int it = 0; it < SS / 128; ++it) {
        const int i = it * 128 + tid;
        const int p = __popcll(qbit ^ __ldg(&kb[i]));
        s_popc[i] = (unsigned char)p;
        unsigned grp = __match_any_sync(full, p);
        int leader = __ffs(grp) - 1;
        if (lane == leader) atomicAdd(&s_hist[p], __popc(grp));
    }
    __syncthreads();

    // ---- threshold: smallest p* with cum >= KP ----
    if (tid == 0) {
        int c = 0, pstar = 64, cl = 0;
        for (int p = 0; p <= 64; ++p) {
            int nc = c + s_hist[p];
            if (nc >= KP) { pstar = p; cl = c; break; }
            c = nc;
        }
        s_thresh[0] = pstar;
        s_thresh[1] = KP - cl;   // r keys to take at the tie level
    }
    __syncthreads();
    const int pstar = s_thresh[0];
    const int r     = s_thresh[1];

    // ---- Phase B1: all keys strictly above threshold (set semantics) ----
    const unsigned lt_mask = (1u << lane) - 1u;
    #pragma unroll
    for (int it = 0; it < SS / 128; ++it) {
        const int i = it * 128 + tid;
        const bool take = ((int)s_popc[i] < pstar);
        unsigned ball = __ballot_sync(full, take);
        if (ball) {
            int base;
            if (lane == 0) base = atomicAdd(&s_count, __popc(ball));
            base = __shfl_sync(full, base, 0);
            if (take) s_idx[base + __popc(ball & lt_mask)] = i;
        }
    }
    __syncthreads();

    // ---- Phase B2: first r tied keys by ascending index (warp 0 scan) ----
    if (w == 0) {
        const int base = s_count;       // == KP - r
        int taken = 0;
        for (int c0 = 0; c0 < SS && taken < r; c0 += 32) {
            int i = c0 + lane;
            bool eq = ((int)s_popc[i] == pstar);
            unsigned ball = __ballot_sync(full, eq);
            int pre = __popc(ball & lt_mask);
            if (eq && (taken + pre) < r)
                s_idx[base + taken + pre] = i;
            taken += __popc(ball);
        }
    }
    __syncthreads();

    // ---- Phase C1: precise scores. 2 rows per warp, float4 lanes ----
    const float* kbase = k + (size_t)bh * SS * DD;
    const float* mrow  = mask + (size_t)b * SS;
    {
        const int l16  = lane & 15;
        const int half = lane >> 4;
        const float4 qv = s_q4[l16];
        for (int j = w * 2 + half; j < KP; j += 8) {
            const int idx = s_idx[j];
            const float4 kv = ((const float4*)(kbase + (size_t)idx * DD))[l16];
            float part = qv.x * kv.x + qv.y * kv.y + qv.z * kv.z + qv.w * kv.w;
            #pragma unroll
            for (int off = 8; off; off >>= 1)
                part += __shfl_xor_sync(full, part, off);
            if (l16 == 0)
                s_score[j] = part * 0.125f + mrow[idx];
        }
    }
    __syncthreads();

    // ---- softmax max ----
    float vmax = (tid < KP) ? s_score[tid] : -INFINITY;
    #pragma unroll
    for (int off = 16; off; off >>= 1)
        vmax = fmaxf(vmax, __shfl_xor_sync(full, vmax, off));
    if (lane == 0) s_red[w] = vmax;
    __syncthreads();
    const float m = fmaxf(fmaxf(s_red[0], s_red[1]), fmaxf(s_red[2], s_red[3]));
    __syncthreads();

    // ---- exp + sum ----
    float e = (tid < KP) ? __expf(s_score[tid] - m) : 0.0f;
    if (tid < KP) s_score[tid] = e;
    float sm = e;
    #pragma unroll
    for (int off = 16; off; off >>= 1)
        sm += __shfl_xor_sync(full, sm, off);
    if (lane == 0) s_red[w] = sm;
    __syncthreads();
    const float inv = 1.0f / (s_red[0] + s_red[1] + s_red[2] + s_red[3]);

    // ---- Phase C2: weighted v accumulation, float4, 8 key-groups ----
    const float* vbase = v + (size_t)bh * SS * DD;
    {
        const int g   = tid >> 4;    // 0..7
        const int l16 = tid & 15;
        float4 acc = make_float4(0.f, 0.f, 0.f, 0.f);
        for (int j = g; j < KP; j += 8) {
            const float p = s_score[j];
            const float4 vv = ((const float4*)(vbase + (size_t)s_idx[j] * DD))[l16];
            acc.x += p * vv.x;
            acc.y += p * vv.y;
            acc.z += p * vv.z;
            acc.w += p * vv.w;
        }
        ((float4*)&s_accf[g][0])[l16] = acc;
    }
    __syncthreads();
    if (tid < DD) {
        float s = 0.0f;
        #pragma unroll
        for (int g = 0; g < 8; ++g) s += s_accf[g][tid];
        out[(size_t)qid * DD + tid] = s * inv;
    }
}

// ---------------------------------------------------------------------------
extern "C" void kernel_launch(void* const* d_in, const int* in_sizes, int n_in,
                              void* d_out, int out_size) {
    const float* q    = (const float*)d_in[0];
    const float* k    = (const float*)d_in[1];
    const float* v    = (const float*)d_in[2];
    const float* mask = (const float*)d_in[3];
    float* out        = (float*)d_out;

    {
        int total_threads = 2 * NROWS * 32;
        int block = 256;
        int grid = (total_threads + block - 1) / block;
        pack_signs_kernel<<<grid, block>>>(q, k);
    }
    attn_kernel<<<NROWS, 128>>>(q, k, v, mask, out);
}